// round 15
// baseline (speedup 1.0000x reference)
#include <cuda_runtime.h>

#define NBINS 15
#define C 50
#define TPB 128                      // 4 warps per block
#define WARPS 4
#define WROWS 16                     // rows per warp-tile (2 lanes per row)
#define WTILE_BYTES (WROWS * C * 4)  // 3200
#define WTILE_F4 (WTILE_BYTES / 16)  // 200 float4
#define GRID_BLOCKS 1216             // 8 blocks/SM x 152 SMs

// Global accumulators: [0..14]=count, [15..29]=sum_acc, [30..44]=sum_conf
// Zero at module load; the finalizing block resets them each run (replay-safe).
__device__ float g_bins[3 * NBINS];
__device__ unsigned int g_ticket;

__global__ __launch_bounds__(TPB) void ece_half_row_kernel(
    const float* __restrict__ logits,
    const int* __restrict__ labels,
    float* __restrict__ out,
    int N, int n_tiles)
{
    // Per-warp double-buffered 3200B tiles; warps fully decoupled in the loop.
    extern __shared__ float4 buf[];              // [WARPS * 2 * WTILE_F4]
    __shared__ float s_bins[3 * NBINS];
    __shared__ int s_last;
    __shared__ __align__(8) unsigned long long s_mbar[WARPS * 2];

    int t = threadIdx.x;
    int wid = t >> 5;
    int lane = t & 31;
    int half = lane & 1;      // 0: float2 k=0..11 (24 floats), 1: k=12..24 (26)
    int r    = lane >> 1;     // row within tile (0..15)
    if (t < 3 * NBINS) s_bins[t] = 0.0f;

    unsigned mb_base = (unsigned)__cvta_generic_to_shared(&s_mbar[wid * 2]);
    float4* wbuf = buf + wid * 2 * WTILE_F4;

    if (lane == 0) {
        asm volatile("mbarrier.init.shared.b64 [%0], 1;" :: "r"(mb_base) : "memory");
        asm volatile("mbarrier.init.shared.b64 [%0], 1;" :: "r"(mb_base + 8) : "memory");
    }
    __syncthreads();   // covers mbarrier init + s_bins zero

    const int gwarp  = blockIdx.x * WARPS + wid;
    const int stride = gridDim.x * WARPS;

    // Prologue: prefetch first warp-tile into stage 0.
    if (lane == 0 && gwarp < n_tiles && (gwarp + 1) * WROWS <= N) {
        asm volatile("mbarrier.arrive.expect_tx.shared.b64 _, [%0], %1;"
                     :: "r"(mb_base), "r"((unsigned)WTILE_BYTES) : "memory");
        unsigned dst = (unsigned)__cvta_generic_to_shared(wbuf);
        asm volatile(
            "cp.async.bulk.shared::cta.global.mbarrier::complete_tx::bytes "
            "[%0], [%1], %2, [%3];"
            :: "r"(dst), "l"(logits + (size_t)gwarp * WROWS * C),
               "r"((unsigned)WTILE_BYTES), "r"(mb_base) : "memory");
    }

    int ph0 = 0, ph1 = 0;
    int cur = 0;

    for (int tile = gwarp; tile < n_tiles; tile += stride) {
        int row0  = tile * WROWS;
        int nrows = min(WROWS, N - row0);
        bool fullt = (nrows == WROWS);

        // Prefetch NEXT tile into the other stage (consumed last iteration;
        // the pair-combine shfl there converged the warp; all LDS results were
        // consumed by lane dataflow before that, so overwrite is safe).
        int nxt = tile + stride;
        if (lane == 0 && nxt < n_tiles && (nxt + 1) * WROWS <= N) {
            unsigned mbn = mb_base + 8u * (unsigned)(cur ^ 1);
            asm volatile("mbarrier.arrive.expect_tx.shared.b64 _, [%0], %1;"
                         :: "r"(mbn), "r"((unsigned)WTILE_BYTES) : "memory");
            unsigned dst = (unsigned)__cvta_generic_to_shared(
                               wbuf + (cur ^ 1) * WTILE_F4);
            asm volatile(
                "cp.async.bulk.shared::cta.global.mbarrier::complete_tx::bytes "
                "[%0], [%1], %2, [%3];"
                :: "r"(dst), "l"(logits + (size_t)nxt * WROWS * C),
                   "r"((unsigned)WTILE_BYTES), "r"(mbn) : "memory");
        }

        int lbl = 0;
        if (r < nrows) lbl = labels[row0 + r];   // pair-duplicated, coalesced

        const float* base;                        // this tile's 16x50 floats
        if (fullt) {
            unsigned mbc = mb_base + 8u * (unsigned)cur;
            int ph = cur ? ph1 : ph0;
            asm volatile(
                "{\n\t"
                ".reg .pred p;\n\t"
                "WAIT_%=:\n\t"
                "mbarrier.try_wait.parity.acquire.cta.shared::cta.b64 p, [%0], %1, 0x989680;\n\t"
                "@!p bra WAIT_%=;\n\t"
                "}"
                :: "r"(mbc), "r"((unsigned)ph) : "memory");
            if (cur) ph1 ^= 1; else ph0 ^= 1;
            base = reinterpret_cast<const float*>(wbuf + cur * WTILE_F4);
        } else {
            base = logits + (size_t)row0 * C;     // rare tail: straight from L2
        }

        if (r < nrows) {
            // Each lane: its half-row. k0 = 12 float2 common; odd half has a 13th.
            const float2* my = reinterpret_cast<const float2*>(base)
                               + r * (C / 2) + half * 12;
            float2 q = my[0];
            float mx0 = q.x, mx1 = q.y;
            float se0 = __expf(q.x), se1 = __expf(q.y);
            #pragma unroll
            for (int k = 1; k < 12; k++) {
                q = my[k];
                mx0 = fmaxf(mx0, q.x);
                mx1 = fmaxf(mx1, q.y);
                se0 += __expf(q.x);
                se1 += __expf(q.y);
            }
            if (half) {                     // odd lane's 13th float2 (floats 48,49)
                q = my[12];
                mx0 = fmaxf(mx0, q.x);
                mx1 = fmaxf(mx1, q.y);
                se0 += __expf(q.x);
                se1 += __expf(q.y);
            }
            float mx = fmaxf(mx0, mx1);
            float se = se0 + se1;

            // Pair combine (lane r*2 <-> r*2+1)
            mx = fmaxf(mx, __shfl_xor_sync(0xffffffffu, mx, 1));
            se += __shfl_xor_sync(0xffffffffu, se, 1);

            if (!half) {
                float conf = __expf(mx) / se;          // max softmax prob
                float lv = base[r * C + lbl];          // label's logit
                float accv = (lv == mx) ? 1.0f : 0.0f; // unique-max equality

                int bin = (int)ceilf(conf * (float)NBINS) - 1;
                bin = min(max(bin, 0), NBINS - 1);

                atomicAdd(&s_bins[bin], 1.0f);
                atomicAdd(&s_bins[NBINS + bin], accv);
                atomicAdd(&s_bins[2 * NBINS + bin], conf);
            }
        }

        cur ^= 1;
    }

    // ---- Flush per-block totals once ----
    __syncthreads();
    if (t < 3 * NBINS) {
        float v = s_bins[t];
        if (v != 0.0f) atomicAdd(&g_bins[t], v);
    }
    __threadfence();
    __syncthreads();

    if (t == 0) {
        unsigned int old = atomicAdd(&g_ticket, 1u);
        s_last = (old == gridDim.x - 1) ? 1 : 0;
    }
    __syncthreads();

    if (s_last && t == 0) {
        __threadfence();
        float bins[3 * NBINS];
        for (int i = 0; i < 3 * NBINS; i++)
            bins[i] = atomicAdd(&g_bins[i], 0.0f);   // read through L2

        float invN = 1.0f / (float)N;
        float ece = 0.0f;
        for (int i = 0; i < NBINS; i++) {
            float cntf = bins[i];
            float sa   = bins[NBINS + i];
            float sc   = bins[2 * NBINS + i];
            float prop = cntf * invN;
            float denom = fmaxf(cntf, 1.0f);
            float gap = (sc - sa) / denom;
            bool nonempty = cntf > 0.0f;
            out[1 + i]  = nonempty ? gap * prop : 0.0f;   // bin_over_confidence
            out[16 + i] = prop;                            // prop_in_bin
            if (nonempty) ece += fabsf(gap) * prop;
        }
        out[0] = ece;

        // Reset device state for the next graph replay (deterministic).
        for (int i = 0; i < 3 * NBINS; i++) g_bins[i] = 0.0f;
        g_ticket = 0u;
        __threadfence();
    }
}

extern "C" void kernel_launch(void* const* d_in, const int* in_sizes, int n_in,
                              void* d_out, int out_size)
{
    // Identify inputs by element count (logits has C=50x more elements).
    const float* logits;
    const int*   labels;
    int N;
    if (in_sizes[0] > in_sizes[1]) {
        logits = (const float*)d_in[0];
        labels = (const int*)d_in[1];
        N = in_sizes[1];
    } else {
        logits = (const float*)d_in[1];
        labels = (const int*)d_in[0];
        N = in_sizes[0];
    }
    float* out = (float*)d_out;

    int n_tiles = (N + WROWS - 1) / WROWS;
    int blocks = GRID_BLOCKS;
    if (n_tiles < GRID_BLOCKS * WARPS)
        blocks = (n_tiles + WARPS - 1) / WARPS;

    size_t dyn = (size_t)WARPS * 2 * WTILE_BYTES;   // 25600 B

    static int attr_set = 0;    // idempotent attribute config (not a work guard)
    if (!attr_set) {
        cudaFuncSetAttribute(ece_half_row_kernel,
                             cudaFuncAttributeMaxDynamicSharedMemorySize, (int)dyn);
        attr_set = 1;
    }

    ece_half_row_kernel<<<blocks, TPB, dyn>>>(logits, labels, out, N, n_tiles);
}

// round 16
// speedup vs baseline: 1.1996x; 1.1996x over previous
#include <cuda_runtime.h>

#define NBINS 15
#define C 50
#define TPB 128                      // 4 warps per block
#define WARPS 4
#define WROWS 16                     // rows per warp-tile (2 lanes per row)
#define WTILE_BYTES (WROWS * C * 4)  // 3200
#define WTILE_F4 (WTILE_BYTES / 16)  // 200 float4
#define GRID_BLOCKS 1216             // 8 blocks/SM x 152 SMs

// Global accumulators: [0..14]=count, [15..29]=sum_acc, [30..44]=sum_conf
// Zero at module load; the finalizing block resets them each run (replay-safe).
__device__ float g_bins[3 * NBINS];
__device__ unsigned int g_ticket;

__global__ __launch_bounds__(TPB) void ece_half_agg_kernel(
    const float* __restrict__ logits,
    const int* __restrict__ labels,
    float* __restrict__ out,
    int N, int n_tiles)
{
    // Per-warp double-buffered 3200B tiles; warps fully decoupled in the loop.
    extern __shared__ float4 buf[];              // [WARPS * 2 * WTILE_F4]
    __shared__ float s_bins[3 * NBINS];
    __shared__ int s_last;
    __shared__ __align__(8) unsigned long long s_mbar[WARPS * 2];

    int t = threadIdx.x;
    int wid = t >> 5;
    int lane = t & 31;
    int half = lane & 1;      // 0: float2 k=0..11, 1: k=12..24
    int r    = lane >> 1;     // row within tile (0..15)
    if (t < 3 * NBINS) s_bins[t] = 0.0f;

    unsigned mb_base = (unsigned)__cvta_generic_to_shared(&s_mbar[wid * 2]);
    float4* wbuf = buf + wid * 2 * WTILE_F4;

    if (lane == 0) {
        asm volatile("mbarrier.init.shared.b64 [%0], 1;" :: "r"(mb_base) : "memory");
        asm volatile("mbarrier.init.shared.b64 [%0], 1;" :: "r"(mb_base + 8) : "memory");
    }
    __syncthreads();   // covers mbarrier init + s_bins zero

    const int gwarp  = blockIdx.x * WARPS + wid;
    const int stride = gridDim.x * WARPS;

    // Prologue: prefetch first warp-tile into stage 0.
    if (lane == 0 && gwarp < n_tiles && (gwarp + 1) * WROWS <= N) {
        asm volatile("mbarrier.arrive.expect_tx.shared.b64 _, [%0], %1;"
                     :: "r"(mb_base), "r"((unsigned)WTILE_BYTES) : "memory");
        unsigned dst = (unsigned)__cvta_generic_to_shared(wbuf);
        asm volatile(
            "cp.async.bulk.shared::cta.global.mbarrier::complete_tx::bytes "
            "[%0], [%1], %2, [%3];"
            :: "r"(dst), "l"(logits + (size_t)gwarp * WROWS * C),
               "r"((unsigned)WTILE_BYTES), "r"(mb_base) : "memory");
    }

    int ph0 = 0, ph1 = 0;
    int cur = 0;

    for (int tile = gwarp; tile < n_tiles; tile += stride) {
        int row0  = tile * WROWS;
        int nrows = min(WROWS, N - row0);
        bool fullt = (nrows == WROWS);

        // Prefetch NEXT tile into the other stage (consumed last iteration;
        // the aggregation shfl there converged the warp and all LDS results
        // were consumed by lane dataflow, so overwrite is safe).
        int nxt = tile + stride;
        if (lane == 0 && nxt < n_tiles && (nxt + 1) * WROWS <= N) {
            unsigned mbn = mb_base + 8u * (unsigned)(cur ^ 1);
            asm volatile("mbarrier.arrive.expect_tx.shared.b64 _, [%0], %1;"
                         :: "r"(mbn), "r"((unsigned)WTILE_BYTES) : "memory");
            unsigned dst = (unsigned)__cvta_generic_to_shared(
                               wbuf + (cur ^ 1) * WTILE_F4);
            asm volatile(
                "cp.async.bulk.shared::cta.global.mbarrier::complete_tx::bytes "
                "[%0], [%1], %2, [%3];"
                :: "r"(dst), "l"(logits + (size_t)nxt * WROWS * C),
                   "r"((unsigned)WTILE_BYTES), "r"(mbn) : "memory");
        }

        int lbl = 0;
        if (r < nrows) lbl = labels[row0 + r];   // pair-duplicated, coalesced

        const float* base;
        if (fullt) {
            unsigned mbc = mb_base + 8u * (unsigned)cur;
            int ph = cur ? ph1 : ph0;
            asm volatile(
                "{\n\t"
                ".reg .pred p;\n\t"
                "WAIT_%=:\n\t"
                "mbarrier.try_wait.parity.acquire.cta.shared::cta.b64 p, [%0], %1, 0x989680;\n\t"
                "@!p bra WAIT_%=;\n\t"
                "}"
                :: "r"(mbc), "r"((unsigned)ph) : "memory");
            if (cur) ph1 ^= 1; else ph0 ^= 1;
            base = reinterpret_cast<const float*>(wbuf + cur * WTILE_F4);
        } else {
            base = logits + (size_t)row0 * C;     // rare tail: straight from L2
        }

        // Per-lane results; odd lanes and invalid rows park at dummy bin NBINS.
        int bin = NBINS;
        float conf = 0.0f;
        int accb = 0;

        if (r < nrows) {
            // Each lane: its half-row (12 float2 common; odd half has a 13th).
            const float2* my = reinterpret_cast<const float2*>(base)
                               + r * (C / 2) + half * 12;
            float2 q = my[0];
            float mx0 = q.x, mx1 = q.y;
            float se0 = __expf(q.x), se1 = __expf(q.y);
            #pragma unroll
            for (int k = 1; k < 12; k++) {
                q = my[k];
                mx0 = fmaxf(mx0, q.x);
                mx1 = fmaxf(mx1, q.y);
                se0 += __expf(q.x);
                se1 += __expf(q.y);
            }
            if (half) {                     // odd lane's 13th float2 (floats 48,49)
                q = my[12];
                mx0 = fmaxf(mx0, q.x);
                mx1 = fmaxf(mx1, q.y);
                se0 += __expf(q.x);
                se1 += __expf(q.y);
            }
            float mx = fmaxf(mx0, mx1);
            float se = se0 + se1;

            // Pair combine (lane 2r <-> 2r+1)
            mx = fmaxf(mx, __shfl_xor_sync(0xffffffffu, mx, 1));
            se += __shfl_xor_sync(0xffffffffu, se, 1);

            if (!half) {
                conf = __expf(mx) / se;               // max softmax prob
                float lv = base[r * C + lbl];         // label's logit
                accb = (lv == mx) ? 1 : 0;            // unique-max equality

                bin = (int)ceilf(conf * (float)NBINS) - 1;
                bin = min(max(bin, 0), NBINS - 1);
            }
        }

        // Segmented warp aggregation: all intrinsics full-mask & convergent;
        // leaders issue spread-address shared atomics (no same-addr replay).
        unsigned active = 0xffffffffu;
        while (active) {
            int ldr = __ffs(active) - 1;
            int b = __shfl_sync(0xffffffffu, bin, ldr);
            unsigned grp  = __ballot_sync(0xffffffffu, bin == b);
            unsigned agrp = __ballot_sync(0xffffffffu, (bin == b) && accb);
            float x = (bin == b) ? conf : 0.0f;
            x += __shfl_xor_sync(0xffffffffu, x, 16);
            x += __shfl_xor_sync(0xffffffffu, x, 8);
            x += __shfl_xor_sync(0xffffffffu, x, 4);
            x += __shfl_xor_sync(0xffffffffu, x, 2);
            x += __shfl_xor_sync(0xffffffffu, x, 1);
            if (lane == ldr && b < NBINS) {
                atomicAdd(&s_bins[b], (float)__popc(grp));
                atomicAdd(&s_bins[NBINS + b], (float)__popc(agrp));
                atomicAdd(&s_bins[2 * NBINS + b], x);
            }
            active &= ~grp;
        }

        cur ^= 1;
    }

    // ---- Flush per-block totals once ----
    __syncthreads();
    if (t < 3 * NBINS) {
        float v = s_bins[t];
        if (v != 0.0f) atomicAdd(&g_bins[t], v);
    }
    __threadfence();
    __syncthreads();

    if (t == 0) {
        unsigned int old = atomicAdd(&g_ticket, 1u);
        s_last = (old == gridDim.x - 1) ? 1 : 0;
    }
    __syncthreads();

    if (s_last && t == 0) {
        __threadfence();
        float bins[3 * NBINS];
        for (int i = 0; i < 3 * NBINS; i++)
            bins[i] = atomicAdd(&g_bins[i], 0.0f);   // read through L2

        float invN = 1.0f / (float)N;
        float ece = 0.0f;
        for (int i = 0; i < NBINS; i++) {
            float cntf = bins[i];
            float sa   = bins[NBINS + i];
            float sc   = bins[2 * NBINS + i];
            float prop = cntf * invN;
            float denom = fmaxf(cntf, 1.0f);
            float gap = (sc - sa) / denom;
            bool nonempty = cntf > 0.0f;
            out[1 + i]  = nonempty ? gap * prop : 0.0f;   // bin_over_confidence
            out[16 + i] = prop;                            // prop_in_bin
            if (nonempty) ece += fabsf(gap) * prop;
        }
        out[0] = ece;

        // Reset device state for the next graph replay (deterministic).
        for (int i = 0; i < 3 * NBINS; i++) g_bins[i] = 0.0f;
        g_ticket = 0u;
        __threadfence();
    }
}

extern "C" void kernel_launch(void* const* d_in, const int* in_sizes, int n_in,
                              void* d_out, int out_size)
{
    // Identify inputs by element count (logits has C=50x more elements).
    const float* logits;
    const int*   labels;
    int N;
    if (in_sizes[0] > in_sizes[1]) {
        logits = (const float*)d_in[0];
        labels = (const int*)d_in[1];
        N = in_sizes[1];
    } else {
        logits = (const float*)d_in[1];
        labels = (const int*)d_in[0];
        N = in_sizes[0];
    }
    float* out = (float*)d_out;

    int n_tiles = (N + WROWS - 1) / WROWS;
    int blocks = GRID_BLOCKS;
    if (n_tiles < GRID_BLOCKS * WARPS)
        blocks = (n_tiles + WARPS - 1) / WARPS;

    size_t dyn = (size_t)WARPS * 2 * WTILE_BYTES;   // 25600 B

    static int attr_set = 0;    // idempotent attribute config (not a work guard)
    if (!attr_set) {
        cudaFuncSetAttribute(ece_half_agg_kernel,
                             cudaFuncAttributeMaxDynamicSharedMemorySize, (int)dyn);
        attr_set = 1;
    }

    ece_half_agg_kernel<<<blocks, TPB, dyn>>>(logits, labels, out, N, n_tiles);
}